// round 2
// baseline (speedup 1.0000x reference)
#include <cuda_runtime.h>
#include <cuda_fp16.h>
#include <cstdint>
#include <cmath>

#define NN 8192
#define DD 128
#define TI 128      // block tile rows
#define TJ 128      // block tile cols
#define KC 64       // K chunk (2 chunks cover D=128)
#define SROW 72     // padded smem row (halves); 144B stride, ldmatrix conflict-free
#define NBLK (NN / TI)                    // 64
#define NTRI (NBLK * (NBLK + 1) / 2)      // 2080 lower-triangle tiles

// Scratch (device globals: allocation is banned in kernel_launch)
__device__ __half d_X[NN * DD];           // normalized embeddings, fp16 (2 MB)
__device__ float  d_partials[NTRI];       // per-block partials (fully overwritten each call)

// ---------------------------------------------------------------------------
// Kernel 1: row-normalize embeddings -> fp16. One warp per row.
// ---------------------------------------------------------------------------
__global__ void norm_kernel(const float* __restrict__ emb) {
    int warp = (blockIdx.x * blockDim.x + threadIdx.x) >> 5;
    int lane = threadIdx.x & 31;
    const float4 v = reinterpret_cast<const float4*>(emb + (size_t)warp * DD)[lane];
    float ss = v.x * v.x + v.y * v.y + v.z * v.z + v.w * v.w;
    #pragma unroll
    for (int o = 16; o > 0; o >>= 1) ss += __shfl_xor_sync(0xffffffffu, ss, o);
    float scale = 1.0f / fmaxf(sqrtf(ss), 1e-8f);   // eps clamp on the norm
    __half2* dst = reinterpret_cast<__half2*>(d_X + (size_t)warp * DD);
    dst[lane * 2]     = __floats2half2_rn(v.x * scale, v.y * scale);
    dst[lane * 2 + 1] = __floats2half2_rn(v.z * scale, v.w * scale);
}

// ---------------------------------------------------------------------------
// mma.sync helpers (m16n8k16 f16 -> f32)
// ---------------------------------------------------------------------------
__device__ __forceinline__ uint32_t smem_u32(const void* p) {
    return (uint32_t)__cvta_generic_to_shared(p);
}
__device__ __forceinline__ void ldm_x4(uint32_t& r0, uint32_t& r1, uint32_t& r2, uint32_t& r3,
                                       uint32_t a) {
    asm volatile("ldmatrix.sync.aligned.m8n8.x4.shared.b16 {%0,%1,%2,%3}, [%4];"
                 : "=r"(r0), "=r"(r1), "=r"(r2), "=r"(r3) : "r"(a));
}
__device__ __forceinline__ void ldm_x2(uint32_t& r0, uint32_t& r1, uint32_t a) {
    asm volatile("ldmatrix.sync.aligned.m8n8.x2.shared.b16 {%0,%1}, [%2];"
                 : "=r"(r0), "=r"(r1) : "r"(a));
}
__device__ __forceinline__ void mma16816(float* c,
                                         uint32_t a0, uint32_t a1, uint32_t a2, uint32_t a3,
                                         uint32_t b0, uint32_t b1) {
    asm volatile("mma.sync.aligned.m16n8k16.row.col.f32.f16.f16.f32 "
                 "{%0,%1,%2,%3}, {%4,%5,%6,%7}, {%8,%9}, {%0,%1,%2,%3};"
                 : "+f"(c[0]), "+f"(c[1]), "+f"(c[2]), "+f"(c[3])
                 : "r"(a0), "r"(a1), "r"(a2), "r"(a3), "r"(b0), "r"(b1));
}

// ---------------------------------------------------------------------------
// Kernel 2: one lower-triangle C tile (ti<=tj as (col,row) decode), fused with
// epilogue(s): sum((C - S[ti,tj])^2) and, if off-diagonal, sum((C^T - S[tj,ti])^2).
// S is streamed exactly once overall; pred never touches memory.
// Block = 256 threads = 8 warps (4x2), warp tile 32x64.
// ---------------------------------------------------------------------------
__global__ __launch_bounds__(256, 2)
void mse_gemm_kernel(const float* __restrict__ S) {
    __shared__ __half sA[TI * SROW];
    __shared__ __half sB[TJ * SROW];
    __shared__ float wsum[8];

    const int tid  = threadIdx.x;
    const int wid  = tid >> 5;
    const int lane = tid & 31;
    const int warp_m = wid & 3;   // 4 row-slices of 32
    const int warp_n = wid >> 2;  // 2 col-slices of 64

    // Triangular decode: b = row*(row+1)/2 + col, col <= row.
    const int b = blockIdx.x;
    int row = (int)((sqrt((double)(8.0 * b + 1.0)) - 1.0) * 0.5);
    while ((row + 1) * (row + 2) / 2 <= b) row++;
    while (row * (row + 1) / 2 > b) row--;
    const int col = b - row * (row + 1) / 2;
    const int ti = col;           // tile row of C (ti <= tj)
    const int tj = row;           // tile col of C

    float acc[2][8][4];
    #pragma unroll
    for (int a = 0; a < 2; a++)
        #pragma unroll
        for (int bb = 0; bb < 8; bb++)
            #pragma unroll
            for (int c = 0; c < 4; c++) acc[a][bb][c] = 0.f;

    const int rowA0 = ti * TI;
    const int rowB0 = tj * TJ;

    const int a_r = lane & 15;
    const int a_c = (lane >> 4) << 3;
    const int l16 = lane & 15;
    const int b_r = l16 & 7;
    const int b_c = (l16 >> 3) << 3;

    #pragma unroll
    for (int kc = 0; kc < DD / KC; kc++) {
        __syncthreads();
        #pragma unroll
        for (int i = 0; i < 4; i++) {
            int idx = tid + i * 256;
            int r   = idx >> 3;       // 8 uint4 (64 halves) per row
            int c8  = idx & 7;
            *reinterpret_cast<uint4*>(&sA[r * SROW + c8 * 8]) =
                *reinterpret_cast<const uint4*>(d_X + (size_t)(rowA0 + r) * DD + kc * KC + c8 * 8);
            *reinterpret_cast<uint4*>(&sB[r * SROW + c8 * 8]) =
                *reinterpret_cast<const uint4*>(d_X + (size_t)(rowB0 + r) * DD + kc * KC + c8 * 8);
        }
        __syncthreads();

        #pragma unroll
        for (int ks = 0; ks < KC / 16; ks++) {
            const int k0 = ks * 16;
            uint32_t ar[2][4];
            #pragma unroll
            for (int mt = 0; mt < 2; mt++) {
                int r = warp_m * 32 + mt * 16 + a_r;
                ldm_x4(ar[mt][0], ar[mt][1], ar[mt][2], ar[mt][3],
                       smem_u32(&sA[r * SROW + k0 + a_c]));
            }
            uint32_t br[8][2];
            #pragma unroll
            for (int nt = 0; nt < 8; nt++) {
                int r = warp_n * 64 + nt * 8 + b_r;
                ldm_x2(br[nt][0], br[nt][1], smem_u32(&sB[r * SROW + k0 + b_c]));
            }
            #pragma unroll
            for (int mt = 0; mt < 2; mt++)
                #pragma unroll
                for (int nt = 0; nt < 8; nt++)
                    mma16816(acc[mt][nt], ar[mt][0], ar[mt][1], ar[mt][2], ar[mt][3],
                             br[nt][0], br[nt][1]);
        }
    }

    // C fragment coordinates for this lane:
    //   r = ti*128 + warp_m*32 + mt*16 + (lane>>2) [+8 for k>=2]
    //   c = tj*128 + warp_n*64 + nt*8 + 2*(lane&3) [+1 for odd k]
    float local = 0.f;
    const int fr = warp_m * 32 + (lane >> 2);    // local frag row base
    const int fc = warp_n * 64 + (lane & 3) * 2; // local frag col base

    // Epilogue 1: tile S[ti,tj], direct layout (float2 loads, full 32B sectors).
    {
        const int gr0 = ti * TI + fr;
        const int gc0 = tj * TJ + fc;
        #pragma unroll
        for (int mt = 0; mt < 2; mt++) {
            #pragma unroll
            for (int nt = 0; nt < 8; nt++) {
                const int r = gr0 + mt * 16;
                const int c = gc0 + nt * 8;
                float2 s0 = *reinterpret_cast<const float2*>(S + (size_t)r * NN + c);
                float2 s1 = *reinterpret_cast<const float2*>(S + (size_t)(r + 8) * NN + c);
                float e0 = acc[mt][nt][0] - s0.x;
                float e1 = acc[mt][nt][1] - s0.y;
                float e2 = acc[mt][nt][2] - s1.x;
                float e3 = acc[mt][nt][3] - s1.y;
                local += e0 * e0 + e1 * e1 + e2 * e2 + e3 * e3;
            }
        }
    }

    // Epilogue 2 (off-diagonal only): tile S[tj,ti] against C^T.
    // Lane reads S[c][r]: per fixed (lane&3), the 8 quads read 8 consecutive
    // floats in one row -> full 32B sectors, 4 rows per instruction group.
    if (ti != tj) {
        const int gr0 = tj * TJ + fc;   // S row index comes from C's col
        const int gc0 = ti * TI + fr;   // S col index comes from C's row
        #pragma unroll
        for (int mt = 0; mt < 2; mt++) {
            #pragma unroll
            for (int nt = 0; nt < 8; nt++) {
                const int sr = gr0 + nt * 8;        // two consecutive S rows: sr, sr+1
                const int sc = gc0 + mt * 16;       // cols sc and sc+8
                float t0 = S[(size_t)sr * NN + sc];
                float t1 = S[(size_t)(sr + 1) * NN + sc];
                float t2 = S[(size_t)sr * NN + sc + 8];
                float t3 = S[(size_t)(sr + 1) * NN + sc + 8];
                float e0 = acc[mt][nt][0] - t0;
                float e1 = acc[mt][nt][1] - t1;
                float e2 = acc[mt][nt][2] - t2;
                float e3 = acc[mt][nt][3] - t3;
                local += e0 * e0 + e1 * e1 + e2 * e2 + e3 * e3;
            }
        }
    }

    #pragma unroll
    for (int o = 16; o > 0; o >>= 1) local += __shfl_xor_sync(0xffffffffu, local, o);
    if (lane == 0) wsum[wid] = local;
    __syncthreads();
    if (wid == 0) {
        float v = (lane < 8) ? wsum[lane] : 0.f;
        #pragma unroll
        for (int o = 4; o > 0; o >>= 1) v += __shfl_xor_sync(0xffffffffu, v, o);
        if (lane == 0) d_partials[b] = v;
    }
}

// ---------------------------------------------------------------------------
// Kernel 3: deterministic fixed-order reduction of 2080 partials -> loss.
// ---------------------------------------------------------------------------
__global__ void finalize_kernel(float* __restrict__ out) {
    __shared__ float red[256];
    float s = 0.f;
    for (int i = threadIdx.x; i < NTRI; i += 256) s += d_partials[i];
    red[threadIdx.x] = s;
    __syncthreads();
    #pragma unroll
    for (int o = 128; o > 0; o >>= 1) {
        if (threadIdx.x < o) red[threadIdx.x] += red[threadIdx.x + o];
        __syncthreads();
    }
    if (threadIdx.x == 0) out[0] = red[0] / ((float)NN * (float)NN);
}

// ---------------------------------------------------------------------------
extern "C" void kernel_launch(void* const* d_in, const int* in_sizes, int n_in,
                              void* d_out, int out_size) {
    const float* emb = (const float*)d_in[0];   // [8192, 128] fp32
    const float* S   = (const float*)d_in[1];   // [8192, 8192] fp32

    norm_kernel<<<NN / 8, 256>>>(emb);          // one warp per row
    mse_gemm_kernel<<<NTRI, 256>>>(S);
    finalize_kernel<<<1, 256>>>((float*)d_out);
}